// round 5
// baseline (speedup 1.0000x reference)
#include <cuda_runtime.h>
#include <math.h>

// ---------------------------------------------------------------------------
// VectorQuantizer on B200 (sm_100a)
//   x   : [32, 64, 64, 64] float  (B, D, H, W)   N = 32*64*64 = 131072 vectors
//   emb : [1024, 64] float
//   out : [loss (1), z_q (8388608), perplexity (1)]
//
// Bit-exact replication of the reference argmin:
//   dist_nk = fp32( fp32(znorm_n + enorm_k) - 2*dot_nk )
//   znorm, enorm: sequential d=0..63, separate mul+add (no fma)
//   dot: sequential d=0..63, single-accumulator fma
//   argmin: first (lowest k) on ties
// ---------------------------------------------------------------------------

#define KCODES 1024
#define DDIM 64
#define NPOS (32 * 64 * 64)            // 131072
#define TOTAL_ELEMS (NPOS * DDIM)      // 8388608
#define POS_PER_BLOCK 128
#define KCHUNK 128
#define NBLOCKS 1024

#define ZSM_STRIDE 132                 // floats per zsm row  (16B aligned rows)
#define ESM_STRIDE 130                 // floats per esm row  (8B aligned rows)
#define ESM_FLOATS 8320                // 64*130 == 128*65 (reused as zq tile)
#define ZQ_STRIDE 65

__device__ float g_enorm[KCODES];      // ||e_k||^2  (mul+add sequential)
__device__ int   g_counts[KCODES];     // bincount of argmin
__device__ float g_partial[NBLOCKS];   // per-block sum of (z_q - z)^2

// ---- packed f32x2 helpers (Blackwell 2x fp32 path; PTX-only) --------------
__device__ __forceinline__ unsigned long long ffma2(unsigned long long a,
                                                    unsigned long long b,
                                                    unsigned long long c) {
    unsigned long long d;
    asm("fma.rn.f32x2 %0, %1, %2, %3;" : "=l"(d) : "l"(a), "l"(b), "l"(c));
    return d;
}
__device__ __forceinline__ unsigned long long bcast2(float v) {
    unsigned long long r;
    asm("mov.b64 %0, {%1, %1};" : "=l"(r) : "f"(v));
    return r;
}
__device__ __forceinline__ void unpack2(unsigned long long v, float& lo, float& hi) {
    asm("mov.b64 {%0, %1}, %2;" : "=f"(lo), "=f"(hi) : "l"(v));
}

// ---------------------------------------------------------------------------
// prep: zero counts, compute ||e_k||^2 with separate mul+add, sequential
// ---------------------------------------------------------------------------
__global__ void vq_prep(const float* __restrict__ emb) {
    int k = blockIdx.x * blockDim.x + threadIdx.x;
    if (k < KCODES) {
        g_counts[k] = 0;
        float s = 0.0f;
#pragma unroll
        for (int d = 0; d < DDIM; d++) {
            float v = emb[k * DDIM + d];
            s = __fadd_rn(s, __fmul_rn(v, v));
        }
        g_enorm[k] = s;
    }
}

// ---------------------------------------------------------------------------
// main: per block = one batch image x 128 pixels.
//   threads: 256 = 16(tx, code groups of 8) x 16(ty, position groups of 8)
// ---------------------------------------------------------------------------
extern __shared__ float smem[];

__global__ __launch_bounds__(256, 2)
void vq_main(const float* __restrict__ x, const float* __restrict__ emb,
             float* __restrict__ zq_out) {
    float* zsm = smem;                          // [64][ZSM_STRIDE]  z tile, [d][pos]
    float* esm = smem + DDIM * ZSM_STRIDE;      // [64][ESM_STRIDE]  e chunk; reused as zq[128][65]
    int*   msm = (int*)(esm + ESM_FLOATS);      // [128] argmin per position
    float* red = (float*)(msm + POS_PER_BLOCK); // [256] reduction buffer
    float* znsm = red + 256;                    // [128] ||z||^2 per position

    const int tid = threadIdx.x;
    const int tx = tid & 15;       // code group
    const int ty = tid >> 4;       // position group
    const int b = blockIdx.x >> 5;
    const int pos0 = (blockIdx.x & 31) * POS_PER_BLOCK;

    // ---- load + transpose z tile: x[b, c, pos0 + i] -> zsm[c][i] ----------
    const float* xb = x + (size_t)b * DDIM * 4096 + pos0;
    for (int idx = tid; idx < DDIM * POS_PER_BLOCK; idx += 256) {
        int c = idx >> 7, i = idx & 127;
        zsm[c * ZSM_STRIDE + i] = xb[c * 4096 + i];
    }
    __syncthreads();

    // ---- ||z||^2 per position: sequential, separate mul+add ---------------
    if (tid < POS_PER_BLOCK) {
        float s = 0.0f;
#pragma unroll
        for (int d = 0; d < DDIM; d++) {
            float v = zsm[d * ZSM_STRIDE + tid];
            s = __fadd_rn(s, __fmul_rn(v, v));
        }
        znsm[tid] = s;
    }
    __syncthreads();

    float zn[8];
#pragma unroll
    for (int i = 0; i < 8; i++) zn[i] = znsm[ty * 8 + i];

    float bestv[8];
    int   besti[8];
#pragma unroll
    for (int i = 0; i < 8; i++) { bestv[i] = 3.4e38f; besti[i] = 0; }

    for (int chunk = 0; chunk < KCODES / KCHUNK; chunk++) {
        const int kbase = chunk * KCHUNK;
        __syncthreads();   // previous chunk compute done before overwriting esm
        // load + transpose emb chunk: emb[kbase+j][dd] -> esm[dd][j]
        for (int idx = tid; idx < KCHUNK * DDIM; idx += 256) {
            int j = idx >> 6, dd = idx & 63;
            esm[dd * ESM_STRIDE + j] = emb[(kbase + j) * DDIM + dd];
        }
        __syncthreads();

        unsigned long long acc[8][4];
#pragma unroll
        for (int i = 0; i < 8; i++)
#pragma unroll
            for (int j = 0; j < 4; j++) acc[i][j] = 0ull;

#pragma unroll 8
        for (int d = 0; d < DDIM; d++) {
            const float* zr = &zsm[d * ZSM_STRIDE + ty * 8];
            float4 za = *(const float4*)zr;
            float4 zb = *(const float4*)(zr + 4);
            unsigned long long zp[8];
            zp[0] = bcast2(za.x); zp[1] = bcast2(za.y);
            zp[2] = bcast2(za.z); zp[3] = bcast2(za.w);
            zp[4] = bcast2(zb.x); zp[5] = bcast2(zb.y);
            zp[6] = bcast2(zb.z); zp[7] = bcast2(zb.w);
            const unsigned long long* ep =
                (const unsigned long long*)&esm[d * ESM_STRIDE + tx * 8];
            unsigned long long e0 = ep[0], e1 = ep[1], e2 = ep[2], e3 = ep[3];
#pragma unroll
            for (int i = 0; i < 8; i++) {
                acc[i][0] = ffma2(zp[i], e0, acc[i][0]);
                acc[i][1] = ffma2(zp[i], e1, acc[i][1]);
                acc[i][2] = ffma2(zp[i], e2, acc[i][2]);
                acc[i][3] = ffma2(zp[i], e3, acc[i][3]);
            }
        }

        // fold into running argmin over dist = (zn + en) - 2*dot
        // k strictly ascending within thread -> strict < keeps first idx
#pragma unroll
        for (int j = 0; j < 4; j++) {
            const int k0 = kbase + tx * 8 + 2 * j;
            const float el = g_enorm[k0], eh = g_enorm[k0 + 1];
#pragma unroll
            for (int i = 0; i < 8; i++) {
                float lo, hi;
                unpack2(acc[i][j], lo, hi);
                float dl = __fsub_rn(__fadd_rn(zn[i], el), __fmul_rn(2.0f, lo));
                float dh = __fsub_rn(__fadd_rn(zn[i], eh), __fmul_rn(2.0f, hi));
                if (dl < bestv[i]) { bestv[i] = dl; besti[i] = k0; }
                if (dh < bestv[i]) { bestv[i] = dh; besti[i] = k0 + 1; }
            }
        }
    }

    // ---- cross-tx reduction: min value, lowest index on ties --------------
#pragma unroll
    for (int i = 0; i < 8; i++) {
        float v = bestv[i];
        int ix = besti[i];
#pragma unroll
        for (int off = 1; off < 16; off <<= 1) {
            float ov = __shfl_xor_sync(0xffffffffu, v, off);
            int   oi = __shfl_xor_sync(0xffffffffu, ix, off);
            if (ov < v || (ov == v && oi < ix)) { v = ov; ix = oi; }
        }
        bestv[i] = v; besti[i] = ix;
    }
    __syncthreads();   // all threads done reading esm before we overwrite it
    if (tx == 0) {
#pragma unroll
        for (int i = 0; i < 8; i++) {
            msm[ty * 8 + i] = besti[i];
            atomicAdd(&g_counts[besti[i]], 1);
        }
    }
    __syncthreads();

    // ---- gather z_q into smem (reuse esm region) + loss partial -----------
    float* zq = esm;   // [128][ZQ_STRIDE]
    float lsum = 0.0f;
    for (int idx = tid; idx < POS_PER_BLOCK * DDIM; idx += 256) {
        int p = idx >> 6, dd = idx & 63;
        float v = emb[msm[p] * DDIM + dd];
        zq[p * ZQ_STRIDE + dd] = v;
        float diff = v - zsm[dd * ZSM_STRIDE + p];
        lsum = fmaf(diff, diff, lsum);
    }
    red[tid] = lsum;
    __syncthreads();
    for (int s = 128; s > 0; s >>= 1) {
        if (tid < s) red[tid] += red[tid + s];
        __syncthreads();
    }
    if (tid == 0) g_partial[blockIdx.x] = red[0];

    // ---- write z_q transposed back: zq_out[b, dd, pos0 + p] ---------------
    float* ob = zq_out + (size_t)b * DDIM * 4096 + pos0;
    for (int idx = tid; idx < DDIM * POS_PER_BLOCK; idx += 256) {
        int dd = idx >> 7, p = idx & 127;
        ob[dd * 4096 + p] = zq[p * ZQ_STRIDE + dd];
    }
}

// ---------------------------------------------------------------------------
// finalize: deterministic-order loss sum + perplexity
// ---------------------------------------------------------------------------
__global__ void vq_finalize(float* __restrict__ out, int out_size) {
    __shared__ double sred[256];
    const int tid = threadIdx.x;

    double s = 0.0;
    for (int i = tid; i < NBLOCKS; i += 256) s += (double)g_partial[i];
    sred[tid] = s;
    __syncthreads();
    for (int st = 128; st > 0; st >>= 1) {
        if (tid < st) sred[tid] += sred[tid + st];
        __syncthreads();
    }
    const double totalLoss = sred[0];
    __syncthreads();

    double e = 0.0;
    for (int i = tid; i < KCODES; i += 256) {
        double p = (double)g_counts[i] / (double)NPOS;
        e += p * log(p + 1e-10);
    }
    sred[tid] = e;
    __syncthreads();
    for (int st = 128; st > 0; st >>= 1) {
        if (tid < st) sred[tid] += sred[tid + st];
        __syncthreads();
    }
    if (tid == 0) {
        out[0] = (float)(1.25 * totalLoss / (double)TOTAL_ELEMS);
        out[out_size - 1] = (float)exp(-sred[0]);
    }
}

// ---------------------------------------------------------------------------
extern "C" void kernel_launch(void* const* d_in, const int* in_sizes, int n_in,
                              void* d_out, int out_size) {
    const float* x = (const float*)d_in[0];
    const float* emb = (const float*)d_in[1];
    // robustness: detect swapped input order via element counts
    if (n_in >= 2 && in_sizes[0] == KCODES * DDIM && in_sizes[1] == TOTAL_ELEMS) {
        x = (const float*)d_in[1];
        emb = (const float*)d_in[0];
    }
    float* out = (float*)d_out;

    // output layout: [loss, z_q, perplexity] if room for scalars, else just z_q
    const bool has_scalars = (out_size > TOTAL_ELEMS + 1);
    float* zq_base = has_scalars ? (out + 1) : out;

    const int smemBytes = (DDIM * ZSM_STRIDE + ESM_FLOATS) * 4   // zsm + esm/zq
                        + POS_PER_BLOCK * 4                      // msm
                        + 256 * 4                                // red
                        + POS_PER_BLOCK * 4;                     // znsm
    cudaFuncSetAttribute((const void*)vq_main,
                         cudaFuncAttributeMaxDynamicSharedMemorySize, smemBytes);

    vq_prep<<<4, 256>>>(emb);
    vq_main<<<NBLOCKS, 256, smemBytes>>>(x, emb, zq_base);
    if (has_scalars) vq_finalize<<<1, 256>>>(out, out_size);
}